// round 4
// baseline (speedup 1.0000x reference)
#include <cuda_runtime.h>
#include <cuda_bf16.h>
#include <cstdint>

#define BATCH   32768
#define DIMD    128
#define OUTDIM  192
#define NSTEPS  3
#define BN_EPS  1e-5f

// ---------------- device scratch (no allocations allowed) ----------------
__device__ float g_sum[DIMD];
__device__ float g_sumsq[DIMD];
__device__ float g_mloss;
__device__ float g_xn[(size_t)BATCH * DIMD];   // normalized input (16 MB)

// ---------------- helpers ----------------
__device__ __forceinline__ float wsum(float v) {
#pragma unroll
    for (int o = 16; o > 0; o >>= 1) v += __shfl_xor_sync(0xffffffffu, v, o);
    return v;
}
__device__ __forceinline__ float wmax(float v) {
#pragma unroll
    for (int o = 16; o > 0; o >>= 1) v = fmaxf(v, __shfl_xor_sync(0xffffffffu, v, o));
    return v;
}
__device__ __forceinline__ float sigf(float x) {
    return 1.0f / (1.0f + __expf(-x));
}

// ---------------- GLU GEMM + GhostBN building block ----------------
// One warp computes 4 GLU column-pairs (a-cols j0..j0+3, gates j0+192..) for all
// 128 rows of the chunk. Lane owns rows {lane, lane+32, lane+64, lane+96}.
// A is stored transposed + swizzled: sA[k*128 + (row ^ (k&31))].
// MODE 0: write GLU out to sOut (h1T, transposed swizzled)
// MODE 1: write sigmoid(GLU out) to global outp (decoder final, cols 0..63)
// MODE 2: att update in sOut(=sAtt): att = 1.3*sig(o)*(1 - max(att_old - tau, 0))
template<int K, int MODE>
__device__ __forceinline__ void glu_pass(
    const float* __restrict__ sA,
    const float* __restrict__ W,     // [384][K] row-major
    const float* __restrict__ gv,    // gamma [384]
    const float* __restrict__ bv,    // beta  [384]
    int j0, int lane,
    float* sOut, const float* sTau, float* outp)
{
    float acc[8][4];
#pragma unroll
    for (int i = 0; i < 8; i++)
#pragma unroll
        for (int r = 0; r < 4; r++) acc[i][r] = 0.0f;

    float wa[4], wg[4];
#pragma unroll
    for (int c = 0; c < 4; c++) {
        wa[c] = __ldg(W + (j0 + c) * K + lane);
        wg[c] = __ldg(W + (j0 + c + OUTDIM) * K + lane);
    }

#pragma unroll 1
    for (int k0 = 0; k0 < K; k0 += 32) {
        float nwa[4], nwg[4];
        if (k0 + 32 < K) {
#pragma unroll
            for (int c = 0; c < 4; c++) {
                nwa[c] = __ldg(W + (j0 + c) * K + k0 + 32 + lane);
                nwg[c] = __ldg(W + (j0 + c + OUTDIM) * K + k0 + 32 + lane);
            }
        } else {
#pragma unroll
            for (int c = 0; c < 4; c++) { nwa[c] = 0.0f; nwg[c] = 0.0f; }
        }
#pragma unroll
        for (int kk = 0; kk < 32; kk++) {
            const int k = k0 + kk;            // k & 31 == kk (k0 multiple of 32)
            float xv[4];
#pragma unroll
            for (int r = 0; r < 4; r++)
                xv[r] = sA[k * 128 + ((lane + 32 * r) ^ kk)];
#pragma unroll
            for (int c = 0; c < 4; c++) {
                float wac = __shfl_sync(0xffffffffu, wa[c], kk);
                float wgc = __shfl_sync(0xffffffffu, wg[c], kk);
#pragma unroll
                for (int r = 0; r < 4; r++) {
                    acc[c][r]     = fmaf(xv[r], wac, acc[c][r]);
                    acc[4 + c][r] = fmaf(xv[r], wgc, acc[4 + c][r]);
                }
            }
        }
#pragma unroll
        for (int c = 0; c < 4; c++) { wa[c] = nwa[c]; wg[c] = nwg[c]; }
    }

    // ---- epilogue: Ghost-BN (per column over 128 rows, warp allreduce) + GLU ----
    float glu[4][4];
#pragma unroll
    for (int c = 0; c < 4; c++) {
        const int j = j0 + c;
        // a half
        float s = wsum(acc[c][0] + acc[c][1] + acc[c][2] + acc[c][3]);
        float mean = s * (1.0f / 128.0f);
        float d0 = acc[c][0] - mean, d1 = acc[c][1] - mean,
              d2 = acc[c][2] - mean, d3 = acc[c][3] - mean;
        float v = wsum(d0*d0 + d1*d1 + d2*d2 + d3*d3);
        float rstd = rsqrtf(v * (1.0f / 128.0f) + BN_EPS);
        float ga = __ldg(gv + j) * rstd, ba = __ldg(bv + j);
        // g half
        float s2 = wsum(acc[4+c][0] + acc[4+c][1] + acc[4+c][2] + acc[4+c][3]);
        float mean2 = s2 * (1.0f / 128.0f);
        float e0 = acc[4+c][0] - mean2, e1 = acc[4+c][1] - mean2,
              e2 = acc[4+c][2] - mean2, e3 = acc[4+c][3] - mean2;
        float v2 = wsum(e0*e0 + e1*e1 + e2*e2 + e3*e3);
        float rstd2 = rsqrtf(v2 * (1.0f / 128.0f) + BN_EPS);
        float gg = __ldg(gv + j + OUTDIM) * rstd2, bg = __ldg(bv + j + OUTDIM);
        glu[c][0] = (d0 * ga + ba) * sigf(e0 * gg + bg);
        glu[c][1] = (d1 * ga + ba) * sigf(e1 * gg + bg);
        glu[c][2] = (d2 * ga + ba) * sigf(e2 * gg + bg);
        glu[c][3] = (d3 * ga + ba) * sigf(e3 * gg + bg);
    }

    if (MODE == 0) {
#pragma unroll
        for (int c = 0; c < 4; c++) {
            const int j = j0 + c;
#pragma unroll
            for (int r = 0; r < 4; r++) {
                const int row = lane + 32 * r;
                sOut[j * 128 + (row ^ (j & 31))] = glu[c][r];
            }
        }
    } else if (MODE == 1) {
#pragma unroll
        for (int r = 0; r < 4; r++) {
            const int row = lane + 32 * r;
            float4 o = make_float4(sigf(glu[0][r]), sigf(glu[1][r]),
                                   sigf(glu[2][r]), sigf(glu[3][r]));
            *(float4*)(outp + (size_t)row * 64 + j0) = o;
        }
    } else { // MODE 2
#pragma unroll
        for (int c = 0; c < 4; c++) {
            const int ac = j0 + c - 64;        // att column 0..127
#pragma unroll
            for (int r = 0; r < 4; r++) {
                const int row = lane + 32 * r;
                const int idx = row * 128 + (ac ^ (row & 31));
                float old = sOut[idx];
                float m = fmaxf(old - sTau[row], 0.0f);
                sOut[idx] = 1.3f * sigf(glu[c][r]) * (1.0f - m);
            }
        }
    }
}

// ---------------- pre/post kernels ----------------
__global__ void k_zero() {
    int t = threadIdx.x;
    if (t < DIMD) { g_sum[t] = 0.0f; g_sumsq[t] = 0.0f; }
    if (t == 0) g_mloss = 0.0f;
}

__global__ void k_stats(const float* __restrict__ x) {
    const int col = threadIdx.x;
    const int rb  = blockIdx.x * 128;
    float s = 0.0f, sq = 0.0f;
#pragma unroll 4
    for (int r = 0; r < 128; r++) {
        float v = x[(size_t)(rb + r) * DIMD + col];
        s += v; sq = fmaf(v, v, sq);
    }
    atomicAdd(&g_sum[col], s);
    atomicAdd(&g_sumsq[col], sq);
}

__global__ void k_xn(const float* __restrict__ x,
                     const float* __restrict__ gam,
                     const float* __restrict__ bet) {
    const int i4 = blockIdx.x * blockDim.x + threadIdx.x;  // float4 index
    const int c4 = (i4 & 31) << 2;
    float4 xv = ((const float4*)x)[i4];
    float o[4] = {xv.x, xv.y, xv.z, xv.w};
    const float inv = 1.0f / (float)BATCH;
#pragma unroll
    for (int j = 0; j < 4; j++) {
        const int c = c4 + j;
        float mean = g_sum[c] * inv;
        float var  = g_sumsq[c] * inv - mean * mean;
        float rs   = rsqrtf(var + BN_EPS);
        o[j] = (o[j] - mean) * rs * gam[c] + bet[c];
    }
    ((float4*)g_xn)[i4] = make_float4(o[0], o[1], o[2], o[3]);
}

__global__ void k_fin(float* __restrict__ outp) {
    outp[(size_t)NSTEPS * BATCH * 64] = g_mloss * (1.0f / ((float)BATCH * (float)NSTEPS));
}

// ---------------- fused main kernel: one CTA = one 128-row GBN chunk ----------------
#define SMEM_FLOATS (16384 + 16384 + 24576 + 128)
#define SMEM_BYTES  (SMEM_FLOATS * 4)

__global__ void __launch_bounds__(256, 1) tabnet_main(
    const float* __restrict__ encW0, const float* __restrict__ encg0, const float* __restrict__ encb0,
    const float* __restrict__ encW1, const float* __restrict__ encg1, const float* __restrict__ encb1,
    const float* __restrict__ decW0, const float* __restrict__ decg0, const float* __restrict__ decb0,
    const float* __restrict__ decW1, const float* __restrict__ decg1, const float* __restrict__ decb1,
    float* __restrict__ outp)
{
    extern __shared__ float sm[];
    float* sMaskT = sm;                 // [128][128] transposed swizzled masked_x
    float* sAtt   = sm + 16384;         // [128][128] row-major swizzled att
    float* sH1T   = sm + 32768;         // [192][128] transposed swizzled GLU1 out
    float* sTau   = sm + 57344;         // [128]

    const int t = threadIdx.x, lane = t & 31, w = t >> 5;
    const int chunk = blockIdx.x;

    for (int i = t; i < 16384; i += 256) sAtt[i] = 1.0f;   // prior stays 1
    __syncthreads();

    float mloss = 0.0f;
    const float* xrow = g_xn + (size_t)chunk * 128 * DIMD;

    for (int s = 0; s < NSTEPS; s++) {
        // ---- sparsemax tau per row (Michelot fixed-point; exact) ----
        for (int rr = 0; rr < 16; rr++) {
            const int row = w * 16 + rr;
            float z[4];
#pragma unroll
            for (int c = 0; c < 4; c++) {
                const int col = lane + 32 * c;
                z[c] = sAtt[row * 128 + (col ^ (row & 31))];
            }
            float mx = wmax(fmaxf(fmaxf(z[0], z[1]), fmaxf(z[2], z[3])));
#pragma unroll
            for (int c = 0; c < 4; c++) z[c] -= mx;
            float tau = (wsum(z[0] + z[1] + z[2] + z[3]) - 1.0f) * (1.0f / 128.0f);
            for (int it = 0; it < 32; it++) {
                float sp = 0.0f, kp = 0.0f;
#pragma unroll
                for (int c = 0; c < 4; c++)
                    if (z[c] > tau) { sp += z[c]; kp += 1.0f; }
                sp = wsum(sp); kp = wsum(kp);
                float tn = (sp - 1.0f) / kp;
                if (tn == tau) break;
                tau = tn;
            }
            if (lane == 0) sTau[row] = tau + mx;
        }
        __syncthreads();

        // ---- masked_x (transposed swizzled) + M_loss ----
        for (int rr = 0; rr < 16; rr++) {
            const int row = w * 16 + rr;
            const float tau = sTau[row];
#pragma unroll
            for (int c = 0; c < 4; c++) {
                const int col = lane + 32 * c;
                float a = sAtt[row * 128 + (col ^ (row & 31))];
                float m = fmaxf(a - tau, 0.0f);
                float xv = xrow[row * DIMD + col];
                sMaskT[col * 128 + (row ^ (col & 31))] = m * xv;
                mloss += m * __logf(m + 1e-10f);
            }
        }
        __syncthreads();

        // ---- encoder (only needed for s < 2) ----
        if (s < NSTEPS - 1) {
            const float* W0 = encW0 + (size_t)s * 384 * 128;
            const float* g0 = encg0 + s * 384;
            const float* b0 = encb0 + s * 384;
            for (int p = 0; p < 6; p++)
                glu_pass<128, 0>(sMaskT, W0, g0, b0, (p * 8 + w) * 4, lane, sH1T, sTau, nullptr);
            __syncthreads();
            const float* W1 = encW1 + (size_t)s * 384 * 192;
            const float* g1 = encg1 + s * 384;
            const float* b1 = encb1 + s * 384;
            for (int p = 0; p < 4; p++)
                glu_pass<192, 2>(sH1T, W1, g1, b1, 64 + (p * 8 + w) * 4, lane, sAtt, sTau, nullptr);
            __syncthreads();
        }

        // ---- decoder ----
        {
            const float* W0 = decW0 + (size_t)s * 384 * 128;
            const float* g0 = decg0 + s * 384;
            const float* b0 = decb0 + s * 384;
            for (int p = 0; p < 6; p++)
                glu_pass<128, 0>(sMaskT, W0, g0, b0, (p * 8 + w) * 4, lane, sH1T, sTau, nullptr);
            __syncthreads();
            const float* W1 = decW1 + (size_t)s * 384 * 192;
            const float* g1 = decg1 + s * 384;
            const float* b1 = decb1 + s * 384;
            float* ob = outp + ((size_t)s * BATCH + (size_t)chunk * 128) * 64;
            for (int p = 0; p < 2; p++)
                glu_pass<192, 1>(sH1T, W1, g1, b1, (p * 8 + w) * 4, lane, nullptr, sTau, ob);
            __syncthreads();
        }
    }

    mloss = wsum(mloss);
    if (lane == 0) atomicAdd(&g_mloss, mloss);
}

// ---------------- launch ----------------
extern "C" void kernel_launch(void* const* d_in, const int* in_sizes, int n_in,
                              void* d_out, int out_size) {
    const float* x     = (const float*)d_in[0];
    const float* ig    = (const float*)d_in[1];
    const float* ib    = (const float*)d_in[2];
    const float* encW0 = (const float*)d_in[3];
    const float* encg0 = (const float*)d_in[4];
    const float* encb0 = (const float*)d_in[5];
    const float* encW1 = (const float*)d_in[6];
    const float* encg1 = (const float*)d_in[7];
    const float* encb1 = (const float*)d_in[8];
    const float* decW0 = (const float*)d_in[9];
    const float* decg0 = (const float*)d_in[10];
    const float* decb0 = (const float*)d_in[11];
    const float* decW1 = (const float*)d_in[12];
    const float* decg1 = (const float*)d_in[13];
    const float* decb1 = (const float*)d_in[14];
    float* out = (float*)d_out;

    cudaFuncSetAttribute(tabnet_main, cudaFuncAttributeMaxDynamicSharedMemorySize, SMEM_BYTES);

    k_zero<<<1, 128>>>();
    k_stats<<<BATCH / 128, 128>>>(x);
    k_xn<<<(BATCH * DIMD / 4) / 256, 256>>>(x, ig, ib);
    tabnet_main<<<BATCH / 128, 256, SMEM_BYTES>>>(
        encW0, encg0, encb0, encW1, encg1, encb1,
        decW0, decg0, decb0, decW1, decg1, decb1, out);
    k_fin<<<1, 1>>>(out);
}